// round 2
// baseline (speedup 1.0000x reference)
#include <cuda_runtime.h>
#include <math.h>

#define NB    4
#define CCH   128
#define HW    4096            // 64*64 after 2x2 pool
#define KNN   16
#define PAIRS 65536           // HW*KNN per batch
#define NEGINF (-3.4e38f)

// ---------------- scratch (device globals; no allocation allowed) ----------------
__device__ __align__(16) float g_pool[2][NB * CCH * HW];   // NCHW pooled, 16MB
__device__ __align__(16) float g_xt  [2][NB * HW * CCH];   // (N,HW,C) unnormalized, 16MB
__device__ __align__(16) float g_xn  [2][NB * HW * CCH];   // (N,HW,C) normalized, 16MB
__device__ __align__(16) float g_diag[2][NB * HW];
__device__ __align__(16) float g_gram[(size_t)NB * HW * HW];  // 256MB, reused per modality
__device__              int   g_knn [2][NB * PAIRS];
__device__ __align__(16) float g_AB  [4][HW * CCH];        // A_r, B_r, A_i, B_i (batch-0 tables)
__device__ __align__(16) float g_partial[1024][256];
__device__ __align__(16) float g_m   [NB * 256];
__device__ __align__(16) float g_gate[NB * CCH];

// ---------------- 1) maxpool 2x2 on both modalities ----------------
__global__ void k_pool(const float* __restrict__ rgb, const float* __restrict__ ir) {
    int o = blockIdx.x * blockDim.x + threadIdx.x;
    if (o >= NB * CCH * HW) return;
    int x  = o & 63;
    int y  = (o >> 6) & 63;
    int nc = o >> 12;
    int ib = nc * (128 * 128) + (2 * y) * 128 + 2 * x;
    {
        float a = rgb[ib], b = rgb[ib + 1], c = rgb[ib + 128], d = rgb[ib + 129];
        g_pool[0][o] = fmaxf(fmaxf(a, b), fmaxf(c, d));
    }
    {
        float a = ir[ib], b = ir[ib + 1], c = ir[ib + 128], d = ir[ib + 129];
        g_pool[1][o] = fmaxf(fmaxf(a, b), fmaxf(c, d));
    }
}

// ---------------- 2) transpose (n,c,hw) -> (n,hw,c) ----------------
__global__ void k_transpose() {
    __shared__ float s[32][33];
    int mod = blockIdx.z >> 2;
    int n   = blockIdx.z & 3;
    int hw0 = blockIdx.x * 32;
    int c0  = blockIdx.y * 32;
    const float* src = g_pool[mod] + (size_t)n * CCH * HW;
    float*       dst = g_xt[mod]  + (size_t)n * HW * CCH;
#pragma unroll
    for (int r = 0; r < 4; r++) {
        int c = c0 + threadIdx.y + 8 * r;
        s[threadIdx.y + 8 * r][threadIdx.x] = src[c * HW + hw0 + threadIdx.x];
    }
    __syncthreads();
#pragma unroll
    for (int r = 0; r < 4; r++) {
        int hw = hw0 + threadIdx.y + 8 * r;
        dst[hw * CCH + c0 + threadIdx.x] = s[threadIdx.x][threadIdx.y + 8 * r];
    }
}

// ---------------- 3) L2-normalize rows, record diag = ||xn||^2 ----------------
__global__ void k_norm() {
    int mod  = blockIdx.y;
    int row  = blockIdx.x * 8 + (threadIdx.x >> 5);
    int lane = threadIdx.x & 31;
    const float4* src = (const float4*)(g_xt[mod] + (size_t)row * CCH);
    float4*       dst = (float4*)(g_xn[mod] + (size_t)row * CCH);
    float4 v = src[lane];
    float ss = v.x * v.x + v.y * v.y + v.z * v.z + v.w * v.w;
#pragma unroll
    for (int off = 16; off > 0; off >>= 1) ss += __shfl_xor_sync(0xffffffff, ss, off);
    float nrm = sqrtf(ss);
    float inv = 1.0f / fmaxf(nrm, 1e-12f);
    float4 o;
    o.x = v.x * inv; o.y = v.y * inv; o.z = v.z * inv; o.w = v.w * inv;
    dst[lane] = o;
    if (lane == 0) g_diag[mod][row] = ss * inv * inv;
}

// ---------------- 4) symmetric gram: S = Xn * Xn^T (triangular tiles 128x128) --------
__global__ __launch_bounds__(256) void k_gram(int mod) {
    __shared__ float As[128][36];
    __shared__ float Bs[128][36];
    int n = blockIdx.y;
    int t = blockIdx.x;
    int by = (int)((sqrtf(8.0f * t + 1.0f) - 1.0f) * 0.5f);
    while ((by + 1) * (by + 2) / 2 <= t) by++;
    while (by * (by + 1) / 2 > t) by--;
    int bx = t - by * (by + 1) / 2;

    const float* X = g_xn[mod] + (size_t)n * HW * CCH;
    int r0 = by * 128, c0 = bx * 128;
    int tx = threadIdx.x & 15, ty = threadIdx.x >> 4;

    float acc[8][8];
#pragma unroll
    for (int i = 0; i < 8; i++)
#pragma unroll
        for (int j = 0; j < 8; j++) acc[i][j] = 0.0f;

    for (int k0 = 0; k0 < 128; k0 += 32) {
#pragma unroll
        for (int p = 0; p < 4; p++) {
            int f4 = threadIdx.x + 256 * p;
            int r = f4 >> 3, kq = f4 & 7;
            float4 va = *(const float4*)(X + (size_t)(r0 + r) * CCH + k0 + kq * 4);
            *(float4*)(&As[r][kq * 4]) = va;
            float4 vb = *(const float4*)(X + (size_t)(c0 + r) * CCH + k0 + kq * 4);
            *(float4*)(&Bs[r][kq * 4]) = vb;
        }
        __syncthreads();
#pragma unroll 8
        for (int kk = 0; kk < 32; kk++) {
            float a[8], b[8];
#pragma unroll
            for (int i = 0; i < 8; i++) a[i] = As[ty + 16 * i][kk];
#pragma unroll
            for (int j = 0; j < 8; j++) b[j] = Bs[tx + 16 * j][kk];
#pragma unroll
            for (int i = 0; i < 8; i++)
#pragma unroll
                for (int j = 0; j < 8; j++) acc[i][j] += a[i] * b[j];
        }
        __syncthreads();
    }

    float* G = g_gram + (size_t)n * HW * HW;
    // direct write (coalesced)
#pragma unroll
    for (int i = 0; i < 8; i++) {
        int r = r0 + ty + 16 * i;
#pragma unroll
        for (int j = 0; j < 8; j++) G[(size_t)r * HW + c0 + tx + 16 * j] = acc[i][j];
    }
    // mirror write for off-diagonal tiles via smem transpose (coalesced)
    if (bx != by) {
        float* Cs = &As[0][0];   // reuse: need 32*132 = 4224 floats <= 128*36
        for (int cc = 0; cc < 4; cc++) {
            __syncthreads();
#pragma unroll
            for (int jj = 0; jj < 2; jj++) {
                int j = 2 * cc + jj;
                int cloc = tx + 16 * jj;
#pragma unroll
                for (int i = 0; i < 8; i++) Cs[cloc * 132 + ty + 16 * i] = acc[i][j];
            }
            __syncthreads();
#pragma unroll
            for (int p = 0; p < 16; p++) {
                int lin = threadIdx.x + 256 * p;
                int r  = lin & 127;
                int cl = lin >> 7;
                G[(size_t)(c0 + cc * 32 + cl) * HW + r0 + r] = Cs[cl * 132 + r];
            }
        }
    }
}

// ---------------- 5) per-row top-16 by score = 2*r_ij - diag_j ----------------
__global__ __launch_bounds__(128) void k_topk(int mod) {
    __shared__ float sc[HW];
    __shared__ float rv[4];
    __shared__ int   ri[4];
    __shared__ int   sel;
    int n = blockIdx.y, i = blockIdx.x;
    const float* G  = g_gram + (size_t)n * HW * HW + (size_t)i * HW;
    const float* dg = g_diag[mod] + n * HW;
    for (int j = threadIdx.x; j < HW; j += 128)
        sc[j] = 2.0f * G[j] - dg[j];
    __syncthreads();
    int* out = g_knn[mod] + ((size_t)n * HW + i) * KNN;
    for (int s = 0; s < KNN; s++) {
        float best = NEGINF;
        int bidx = HW;
        for (int j = threadIdx.x; j < HW; j += 128) {
            float v = sc[j];
            if (v > best || (v == best && j < bidx)) { best = v; bidx = j; }
        }
#pragma unroll
        for (int off = 16; off > 0; off >>= 1) {
            float ov = __shfl_xor_sync(0xffffffff, best, off);
            int   oi = __shfl_xor_sync(0xffffffff, bidx, off);
            if (ov > best || (ov == best && oi < bidx)) { best = ov; bidx = oi; }
        }
        if ((threadIdx.x & 31) == 0) { rv[threadIdx.x >> 5] = best; ri[threadIdx.x >> 5] = bidx; }
        __syncthreads();
        if (threadIdx.x == 0) {
            float B = rv[0]; int I = ri[0];
#pragma unroll
            for (int w = 1; w < 4; w++)
                if (rv[w] > B || (rv[w] == B && ri[w] < I)) { B = rv[w]; I = ri[w]; }
            out[s] = I;
            sc[I] = NEGINF;
            sel = I;
        }
        __syncthreads();
    }
    (void)sel;
}

// ---------------- 6) A/B tables: 4 GEMMs 4096x128x128 on batch-0 rows ----------------
// which: 0 A_r = Xrgb0@(Wr1+Wr2); 1 B_r = Xir0@Wr2; 2 A_i = Xir0@(Wi1+Wi2); 3 B_i = Xrgb0@Wi2
__global__ __launch_bounds__(256) void k_ab(const float* __restrict__ Wr,
                                            const float* __restrict__ Wi) {
    __shared__ float Xs[64][36];
    __shared__ float Ws[32][128];
    int which = blockIdx.y;
    const float* X  = (which == 0 || which == 3) ? g_xt[0] : g_xt[1]; // batch 0 rows
    const float* Wg = (which < 2) ? Wr : Wi;
    bool both = (which == 0 || which == 2);
    int r0 = blockIdx.x * 64;
    int tx = threadIdx.x & 15, ty = threadIdx.x >> 4;

    float acc[4][8];
#pragma unroll
    for (int i = 0; i < 4; i++)
#pragma unroll
        for (int j = 0; j < 8; j++) acc[i][j] = 0.0f;

    for (int k0 = 0; k0 < 128; k0 += 32) {
#pragma unroll
        for (int p = 0; p < 2; p++) {
            int f4 = threadIdx.x + 256 * p;
            int r = f4 >> 3, kq = f4 & 7;
            *(float4*)(&Xs[r][kq * 4]) =
                *(const float4*)(X + (size_t)(r0 + r) * CCH + k0 + kq * 4);
        }
#pragma unroll
        for (int p = 0; p < 4; p++) {
            int f4 = threadIdx.x + 256 * p;
            int kk = f4 >> 5, cq = f4 & 31;
            float4 w = *(const float4*)(Wg + (size_t)(128 + k0 + kk) * CCH + cq * 4);
            if (both) {
                float4 w0 = *(const float4*)(Wg + (size_t)(k0 + kk) * CCH + cq * 4);
                w.x += w0.x; w.y += w0.y; w.z += w0.z; w.w += w0.w;
            }
            *(float4*)(&Ws[kk][cq * 4]) = w;
        }
        __syncthreads();
#pragma unroll 8
        for (int kk = 0; kk < 32; kk++) {
            float a[4], b[8];
#pragma unroll
            for (int i = 0; i < 4; i++) a[i] = Xs[ty + 16 * i][kk];
#pragma unroll
            for (int j = 0; j < 8; j++) b[j] = Ws[kk][tx + 16 * j];
#pragma unroll
            for (int i = 0; i < 4; i++)
#pragma unroll
                for (int j = 0; j < 8; j++) acc[i][j] += a[i] * b[j];
        }
        __syncthreads();
    }
#pragma unroll
    for (int i = 0; i < 4; i++)
#pragma unroll
        for (int j = 0; j < 8; j++)
            g_AB[which][(size_t)(r0 + ty + 16 * i) * CCH + tx + 16 * j] = acc[i][j];
}

// ---------------- 7) pair gather-mean: partial sums per block ----------------
__global__ __launch_bounds__(128) void k_pair(const float* __restrict__ br,
                                              const float* __restrict__ bi) {
    __shared__ int sp[256], sq[256];
    int n = blockIdx.y;
    int base = n * PAIRS + blockIdx.x * 256;
    for (int t = threadIdx.x; t < 256; t += 128) {
        sp[t] = g_knn[0][base + t];
        sq[t] = g_knn[1][base + t];
    }
    __syncthreads();
    int c = threadIdx.x;
    float brc = br[c], bic = bi[c];
    float aR = 0.0f, aI = 0.0f;
#pragma unroll 4
    for (int t = 0; t < 256; t++) {
        int p = sp[t], q = sq[t];
        float fr = g_AB[0][p * CCH + c] - g_AB[1][q * CCH + c] + brc;
        aR += (fr >= 0.0f) ? fr : 0.01f * fr;
        float fi = g_AB[2][q * CCH + c] - g_AB[3][p * CCH + c] + bic;
        aI += (fi >= 0.0f) ? fi : 0.01f * fi;
    }
    int b = n * 256 + blockIdx.x;
    g_partial[b][c]       = aR;
    g_partial[b][c + 128] = aI;
}

// ---------------- 8) deterministic reduce -> m = mean ----------------
__global__ void k_reduce_m() {
    int n = blockIdx.x, d = threadIdx.x;
    float s = 0.0f;
    for (int bb = 0; bb < 256; bb++) s += g_partial[n * 256 + bb][d];
    g_m[n * 256 + d] = s * (1.0f / (float)PAIRS);
}

// ---------------- 9) SE gate ----------------
__global__ void k_se(const float* __restrict__ w1, const float* __restrict__ b1,
                     const float* __restrict__ w2, const float* __restrict__ b2) {
    __shared__ float tm[NB][8];
    int tid = threadIdx.x;
    if (tid < 32) {
        int n = tid >> 3, j = tid & 7;
        float s = b1[j];
        for (int d = 0; d < 256; d++) s += g_m[n * 256 + d] * w1[d * 8 + j];
        tm[n][j] = (s >= 0.0f) ? s : 0.01f * s;
    }
    __syncthreads();
    int n = tid >> 7, c = tid & 127;
    float s = b2[c];
#pragma unroll
    for (int j = 0; j < 8; j++) s += tm[n][j] * w2[j * 128 + c];
    g_gate[n * 128 + c] = 1.0f / (1.0f + expf(-s));
}

// ---------------- 10) gated blend + relu -> output NCHW ----------------
__global__ void k_out(const float* __restrict__ g1, const float* __restrict__ g2,
                      float* __restrict__ out) {
    int o = blockIdx.x * blockDim.x + threadIdx.x;
    if (o >= NB * CCH * HW) return;
    int nc = o >> 12;
    float g = g_gate[nc];
    float v = g1[0] * g * g_pool[0][o] + g2[0] * (1.0f - g) * g_pool[1][o];
    out[o] = fmaxf(v, 0.0f);
}

// ---------------- launch ----------------
extern "C" void kernel_launch(void* const* d_in, const int* in_sizes, int n_in,
                              void* d_out, int out_size) {
    const float* rgb = (const float*)d_in[0];
    const float* ir  = (const float*)d_in[1];
    const float* Wr  = (const float*)d_in[2];
    const float* br  = (const float*)d_in[3];
    const float* Wi  = (const float*)d_in[4];
    const float* bi  = (const float*)d_in[5];
    const float* w1  = (const float*)d_in[6];
    const float* b1  = (const float*)d_in[7];
    const float* w2  = (const float*)d_in[8];
    const float* b2  = (const float*)d_in[9];
    const float* g1  = (const float*)d_in[10];
    const float* g2  = (const float*)d_in[11];
    float* out = (float*)d_out;

    k_pool<<<8192, 256>>>(rgb, ir);
    k_transpose<<<dim3(128, 4, 8), dim3(32, 8)>>>();
    k_norm<<<dim3(2048, 2), 256>>>();
    k_ab<<<dim3(64, 4), 256>>>(Wr, Wi);

    k_gram<<<dim3(528, 4), 256>>>(0);       // rgb gram (triangular)
    k_topk<<<dim3(4096, 4), 128>>>(0);      // rgb knn
    k_gram<<<dim3(528, 4), 256>>>(1);       // ir gram (buffer reuse, stream-ordered)
    k_topk<<<dim3(4096, 4), 128>>>(1);      // ir knn

    k_pair<<<dim3(256, 4), 128>>>(br, bi);
    k_reduce_m<<<4, 256>>>();
    k_se<<<1, 512>>>(w1, b1, w2, b2);
    k_out<<<8192, 256>>>(g1, g2, out);
}